// round 5
// baseline (speedup 1.0000x reference)
#include <cuda_runtime.h>
#include <cstdint>

#define B_    32
#define CIN   256
#define COUT  512
#define HIN   56
#define WIN   56
#define HOUT  54
#define WOUT  54
#define HWOUT (HOUT * WOUT)          // 2916 = 729 * 4
#define EPS   1e-5f
#define DW_THRESH 4.0f
#define PW_THRESH 0.001f

#define DW_BLOCKS (B_ * CIN)         // 8192
#define PW_BLOCKS (B_ * COUT)        // 16384

// Scratch (device globals: the only allowed scratch mechanism).
__device__ float g_y[(size_t)B_ * CIN * HWOUT];   // depthwise output, written only for survivors
__device__ int   g_flag[B_ * CIN];                // per-(b,c) survival flag
__device__ int   g_done[B_];                      // dw blocks completed per batch (release counter)
__device__ int   g_surv[B_];                      // surviving channels per batch

__device__ __forceinline__ float block_max_256(float v) {
    __shared__ float s_red[8];
    #pragma unroll
    for (int off = 16; off > 0; off >>= 1)
        v = fmaxf(v, __shfl_down_sync(0xffffffffu, v, off));
    if ((threadIdx.x & 31) == 0) s_red[threadIdx.x >> 5] = v;
    __syncthreads();
    if (threadIdx.x < 8) {
        v = s_red[threadIdx.x];
        #pragma unroll
        for (int off = 4; off > 0; off >>= 1)
            v = fmaxf(v, __shfl_down_sync(0xffu, v, off));
        if (threadIdx.x == 0) s_red[0] = v;
    }
    __syncthreads();
    float r = s_red[0];
    __syncthreads();
    return r;
}

// ---------------------------------------------------------------------------
// Init: reset per-batch counters (required per graph replay).
// ---------------------------------------------------------------------------
__global__ void init_kernel()
{
    if (threadIdx.x < B_) {
        g_done[threadIdx.x] = 0;
        g_surv[threadIdx.x] = 0;
    }
}

// ---------------------------------------------------------------------------
// dw role: depthwise 3x3 VALID + bias + BN + ReLU + map-max + cut flag.
// One 256-thread block per (b,c) map; 2 adjacent output columns per thread,
// rolling 3-row register window. Signals completion via g_done[b].
// ---------------------------------------------------------------------------
__device__ __forceinline__
void dw_role(int map,
             const float* __restrict__ x,
             const float* __restrict__ dw_w,
             const float* __restrict__ dw_b,
             const float* __restrict__ dw_gamma,
             const float* __restrict__ dw_beta,
             const float* __restrict__ dw_mean,
             const float* __restrict__ dw_var)
{
    const int c   = map & (CIN - 1);
    const int b   = map >> 8;              // CIN = 256
    const int tid = threadIdx.x;

    __shared__ float tile[HIN * WIN];      // 12.25 KB
    __shared__ float wsh[9];

    {
        const float4* xin4 = (const float4*)(x + (size_t)map * (HIN * WIN));
        float4* t4 = (float4*)tile;
        #pragma unroll
        for (int r = 0; r < 4; r++) {
            const int i = tid + r * 256;
            if (i < (HIN * WIN) / 4) t4[i] = xin4[i];
        }
    }
    if (tid < 9) wsh[tid] = dw_w[c * 9 + tid];
    __syncthreads();

    const float w0 = wsh[0], w1 = wsh[1], w2 = wsh[2];
    const float w3 = wsh[3], w4 = wsh[4], w5 = wsh[5];
    const float w6 = wsh[6], w7 = wsh[7], w8 = wsh[8];

    const float scale = dw_gamma[c] * rsqrtf(dw_var[c] + EPS);
    const float shift = dw_beta[c] - dw_mean[c] * scale;
    const float bias  = dw_b[c];

    const int cp    = tid & 31;            // column pair index, valid < 27
    const int grp   = tid >> 5;            // 0..7
    const int row0  = grp * 7;
    const int nrows = (grp == 7) ? 5 : 7;  // 7*7 + 5 = 54
    const int col   = 2 * cp;
    const bool colok = (cp < 27);

    float vL[7], vR[7];
    float mx = 0.0f;

    if (colok) {
        const float2* prow = (const float2*)(tile + row0 * WIN + col);
        float2 aL = prow[0], aR = prow[1]; prow += WIN / 2;
        float2 bL = prow[0], bR = prow[1]; prow += WIN / 2;
        #pragma unroll
        for (int r = 0; r < 7; r++) {
            if (r < nrows) {
                const float2 cL = prow[0], cR = prow[1]; prow += WIN / 2;
                float accL = aL.x * w0, accR = aL.y * w0;
                accL = fmaf(aL.y, w1, accL);  accR = fmaf(aR.x, w1, accR);
                accL = fmaf(aR.x, w2, accL);  accR = fmaf(aR.y, w2, accR);
                accL = fmaf(bL.x, w3, accL);  accR = fmaf(bL.y, w3, accR);
                accL = fmaf(bL.y, w4, accL);  accR = fmaf(bR.x, w4, accR);
                accL = fmaf(bR.x, w5, accL);  accR = fmaf(bR.y, w5, accR);
                accL = fmaf(cL.x, w6, accL);  accR = fmaf(cL.y, w6, accR);
                accL = fmaf(cL.y, w7, accL);  accR = fmaf(cR.x, w7, accR);
                accL = fmaf(cR.x, w8, accL);  accR = fmaf(cR.y, w8, accR);
                const float zL = fmaxf(fmaf(accL + bias, scale, shift), 0.0f);
                const float zR = fmaxf(fmaf(accR + bias, scale, shift), 0.0f);
                vL[r] = zL; vR[r] = zR;
                mx = fmaxf(mx, fmaxf(zL, zR));
                aL = bL; aR = bR;
                bL = cL; bR = cR;
            }
        }
    }

    const float bmax = block_max_256(mx);
    const int survive = (bmax >= DW_THRESH) ? 1 : 0;

    if (survive && colok) {
        float* yout = g_y + (size_t)map * HWOUT + col;
        #pragma unroll
        for (int r = 0; r < 7; r++)
            if (r < nrows)
                *(float2*)(yout + (row0 + r) * WOUT) = make_float2(vL[r], vR[r]);
    }

    // Publish: flag + survivor count, then release via done-counter.
    if (tid == 0) {
        g_flag[map] = survive;
        if (survive) atomicAdd(&g_surv[b], 1);
    }
    __threadfence();        // each thread's g_y/g_flag writes visible device-wide
    __syncthreads();
    if (tid == 0) atomicAdd(&g_done[b], 1);
}

// ---------------------------------------------------------------------------
// pw role: spin until batch ready, then pointwise GEMM + bias + BN + ReLU + cut.
// cnt==0 fast path: uniform float4 fill (write-only, overlaps with dw reads).
// ---------------------------------------------------------------------------
__device__ __forceinline__
void pw_role(int bo,
             const float* __restrict__ pw_w,
             const float* __restrict__ pw_b,
             const float* __restrict__ pw_gamma,
             const float* __restrict__ pw_beta,
             const float* __restrict__ pw_mean,
             const float* __restrict__ pw_var,
             float* __restrict__ out)
{
    const int o   = bo & (COUT - 1);
    const int bi  = bo >> 9;               // COUT = 512
    const int tid = threadIdx.x;

    __shared__ int s_cnt;

    if (tid == 0) {
        volatile int* done = g_done + bi;
        while (*done < CIN) __nanosleep(128);
        __threadfence();                   // acquire: order subsequent reads
        s_cnt = *((volatile int*)(g_surv + bi));
    }
    __syncthreads();
    const int cnt = s_cnt;

    const float scale = pw_gamma[o] * rsqrtf(pw_var[o] + EPS);
    const float shift = pw_beta[o] - pw_mean[o] * scale;
    const float bias  = pw_b[o];

    float4* op4 = (float4*)(out + (size_t)bo * HWOUT);

    if (cnt == 0) {
        float v = fmaxf(fmaf(bias, scale, shift), 0.0f);
        if (v < PW_THRESH) v = 0.0f;
        const float4 val = make_float4(v, v, v, v);
        #pragma unroll
        for (int r = 0; r < 3; r++) {
            const int idx = tid + r * 256;
            if (idx < HWOUT / 4) op4[idx] = val;     // 729 float4
        }
        return;
    }

    // ---- survivor path (rare): channel GEMM over flagged channels ----
    __shared__ float wrow[CIN];
    __shared__ char  fl[CIN];
    wrow[tid] = pw_w[(size_t)o * CIN + tid];
    fl[tid]   = (char)(g_flag[bi * CIN + tid] != 0);
    __syncthreads();

    float4 acc[3];
    #pragma unroll
    for (int r = 0; r < 3; r++) acc[r] = make_float4(0.f, 0.f, 0.f, 0.f);

    for (int k = 0; k < CIN; k++) {
        if (!fl[k]) continue;
        const float wv = wrow[k];
        const float4* yr4 = (const float4*)(g_y + ((size_t)bi * CIN + k) * HWOUT);
        #pragma unroll
        for (int r = 0; r < 3; r++) {
            const int idx = tid + r * 256;
            if (idx < HWOUT / 4) {
                const float4 yv = yr4[idx];
                acc[r].x = fmaf(yv.x, wv, acc[r].x);
                acc[r].y = fmaf(yv.y, wv, acc[r].y);
                acc[r].z = fmaf(yv.z, wv, acc[r].z);
                acc[r].w = fmaf(yv.w, wv, acc[r].w);
            }
        }
    }

    float4 z[3];
    float mx = 0.0f;
    #pragma unroll
    for (int r = 0; r < 3; r++) {
        z[r].x = fmaxf(fmaf(acc[r].x + bias, scale, shift), 0.0f);
        z[r].y = fmaxf(fmaf(acc[r].y + bias, scale, shift), 0.0f);
        z[r].z = fmaxf(fmaf(acc[r].z + bias, scale, shift), 0.0f);
        z[r].w = fmaxf(fmaf(acc[r].w + bias, scale, shift), 0.0f);
        mx = fmaxf(mx, fmaxf(fmaxf(z[r].x, z[r].y), fmaxf(z[r].z, z[r].w)));
    }

    const float bmax = block_max_256(mx);
    const bool cut = (bmax < PW_THRESH);

    #pragma unroll
    for (int r = 0; r < 3; r++) {
        const int idx = tid + r * 256;
        if (idx < HWOUT / 4)
            op4[idx] = cut ? make_float4(0.f, 0.f, 0.f, 0.f) : z[r];
    }
}

// ---------------------------------------------------------------------------
// Fused kernel: blocks [0, 8192) = dw producers, [8192, 24576) = pw consumers.
// Producer bids precede consumer bids, so dispatch order guarantees forward
// progress; consumers spin with nanosleep backoff on per-batch counters.
// ---------------------------------------------------------------------------
__global__ __launch_bounds__(256, 8)
void fused_kernel(const float* __restrict__ x,
                  const float* __restrict__ dw_w,
                  const float* __restrict__ dw_b,
                  const float* __restrict__ dw_gamma,
                  const float* __restrict__ dw_beta,
                  const float* __restrict__ dw_mean,
                  const float* __restrict__ dw_var,
                  const float* __restrict__ pw_w,
                  const float* __restrict__ pw_b,
                  const float* __restrict__ pw_gamma,
                  const float* __restrict__ pw_beta,
                  const float* __restrict__ pw_mean,
                  const float* __restrict__ pw_var,
                  float* __restrict__ out)
{
    const int bid = blockIdx.x;
    if (bid < DW_BLOCKS) {
        dw_role(bid, x, dw_w, dw_b, dw_gamma, dw_beta, dw_mean, dw_var);
    } else {
        pw_role(bid - DW_BLOCKS, pw_w, pw_b, pw_gamma, pw_beta, pw_mean, pw_var, out);
    }
}

// ---------------------------------------------------------------------------
extern "C" void kernel_launch(void* const* d_in, const int* in_sizes, int n_in,
                              void* d_out, int out_size)
{
    const float* x        = (const float*)d_in[0];
    const float* dw_w     = (const float*)d_in[1];
    const float* dw_b     = (const float*)d_in[2];
    const float* dw_gamma = (const float*)d_in[3];
    const float* dw_beta  = (const float*)d_in[4];
    const float* dw_mean  = (const float*)d_in[5];
    const float* dw_var   = (const float*)d_in[6];
    const float* pw_w     = (const float*)d_in[7];
    const float* pw_b     = (const float*)d_in[8];
    const float* pw_gamma = (const float*)d_in[9];
    const float* pw_beta  = (const float*)d_in[10];
    const float* pw_mean  = (const float*)d_in[11];
    const float* pw_var   = (const float*)d_in[12];
    float* out = (float*)d_out;

    init_kernel<<<1, 32>>>();
    fused_kernel<<<DW_BLOCKS + PW_BLOCKS, 256>>>(
        x, dw_w, dw_b, dw_gamma, dw_beta, dw_mean, dw_var,
        pw_w, pw_b, pw_gamma, pw_beta, pw_mean, pw_var, out);
}

// round 6
// speedup vs baseline: 1.3210x; 1.3210x over previous
#include <cuda_runtime.h>
#include <cstdint>

#define B_    32
#define CIN   256
#define COUT  512
#define HIN   56
#define WIN   56
#define HOUT  54
#define WOUT  54
#define HWOUT (HOUT * WOUT)          // 2916 = 729 * 4
#define EPS   1e-5f
#define DW_THRESH 4.0f
#define PW_THRESH 0.001f

// Scratch (device globals: the only allowed scratch mechanism).
__device__ float g_y[(size_t)B_ * CIN * HWOUT];   // depthwise output, written only for survivors
__device__ int   g_flag[B_ * CIN];                // per-(b,c) survival flag
__device__ int   g_surv[B_];                      // surviving channels per batch

__device__ __forceinline__ float block_max_256(float v) {
    __shared__ float s_red[8];
    #pragma unroll
    for (int off = 16; off > 0; off >>= 1)
        v = fmaxf(v, __shfl_down_sync(0xffffffffu, v, off));
    if ((threadIdx.x & 31) == 0) s_red[threadIdx.x >> 5] = v;
    __syncthreads();
    if (threadIdx.x < 8) {
        v = s_red[threadIdx.x];
        #pragma unroll
        for (int off = 4; off > 0; off >>= 1)
            v = fmaxf(v, __shfl_down_sync(0xffu, v, off));
        if (threadIdx.x == 0) s_red[0] = v;
    }
    __syncthreads();
    float r = s_red[0];
    __syncthreads();
    return r;
}

// ---------------------------------------------------------------------------
// Init: reset per-batch survivor counters (required per graph replay).
// ---------------------------------------------------------------------------
__global__ void init_kernel()
{
    if (threadIdx.x < B_) g_surv[threadIdx.x] = 0;
}

// ---------------------------------------------------------------------------
// Kernel A: depthwise 3x3 VALID + bias + BN + ReLU + map-max + cut flag.
// One 256-thread block per (b,c) map. NO smem tile: each thread reads its
// 4-column window straight from global as two float2 per input row (coalesced
// across lanes; row overlap between groups hits L1). Rolling 3-row register
// window; 2 adjacent output columns per thread.
// ---------------------------------------------------------------------------
__global__ __launch_bounds__(256)
void dw_kernel(const float* __restrict__ x,
               const float* __restrict__ dw_w,
               const float* __restrict__ dw_b,
               const float* __restrict__ dw_gamma,
               const float* __restrict__ dw_beta,
               const float* __restrict__ dw_mean,
               const float* __restrict__ dw_var)
{
    const int map = blockIdx.x;            // b * CIN + c
    const int c   = map & (CIN - 1);
    const int b   = map >> 8;              // CIN = 256
    const int tid = threadIdx.x;

    const float w0 = __ldg(dw_w + c * 9 + 0);
    const float w1 = __ldg(dw_w + c * 9 + 1);
    const float w2 = __ldg(dw_w + c * 9 + 2);
    const float w3 = __ldg(dw_w + c * 9 + 3);
    const float w4 = __ldg(dw_w + c * 9 + 4);
    const float w5 = __ldg(dw_w + c * 9 + 5);
    const float w6 = __ldg(dw_w + c * 9 + 6);
    const float w7 = __ldg(dw_w + c * 9 + 7);
    const float w8 = __ldg(dw_w + c * 9 + 8);

    const float scale = __ldg(dw_gamma + c) * rsqrtf(__ldg(dw_var + c) + EPS);
    const float shift = __ldg(dw_beta + c) - __ldg(dw_mean + c) * scale;
    const float bias  = __ldg(dw_b + c);

    // 32 lanes -> column pairs (27 valid), 8 groups -> row strips (7,...,7,5).
    const int cp    = tid & 31;            // column pair index, valid < 27
    const int grp   = tid >> 5;            // 0..7
    const int row0  = grp * 7;
    const int nrows = (grp == 7) ? 5 : 7;  // 7*7 + 5 = 54
    const int col   = 2 * cp;
    const bool colok = (cp < 27);

    float vL[7], vR[7];
    float mx = 0.0f;

    if (colok) {
        // Global rolling window: two float2 loads per input row cover cols
        // [col, col+3]. 8B-aligned (col even). Lanes coalesce to 256B lines.
        const float2* prow = (const float2*)(x + (size_t)map * (HIN * WIN)
                                               + (size_t)row0 * WIN + col);
        float2 aL = prow[0], aR = prow[1]; prow += WIN / 2;
        float2 bL = prow[0], bR = prow[1]; prow += WIN / 2;
        #pragma unroll
        for (int r = 0; r < 7; r++) {
            if (r < nrows) {
                const float2 cL = prow[0], cR = prow[1]; prow += WIN / 2;
                float accL = aL.x * w0, accR = aL.y * w0;
                accL = fmaf(aL.y, w1, accL);  accR = fmaf(aR.x, w1, accR);
                accL = fmaf(aR.x, w2, accL);  accR = fmaf(aR.y, w2, accR);
                accL = fmaf(bL.x, w3, accL);  accR = fmaf(bL.y, w3, accR);
                accL = fmaf(bL.y, w4, accL);  accR = fmaf(bR.x, w4, accR);
                accL = fmaf(bR.x, w5, accL);  accR = fmaf(bR.y, w5, accR);
                accL = fmaf(cL.x, w6, accL);  accR = fmaf(cL.y, w6, accR);
                accL = fmaf(cL.y, w7, accL);  accR = fmaf(cR.x, w7, accR);
                accL = fmaf(cR.x, w8, accL);  accR = fmaf(cR.y, w8, accR);
                const float zL = fmaxf(fmaf(accL + bias, scale, shift), 0.0f);
                const float zR = fmaxf(fmaf(accR + bias, scale, shift), 0.0f);
                vL[r] = zL; vR[r] = zR;
                mx = fmaxf(mx, fmaxf(zL, zR));     // z >= 0
                aL = bL; aR = bR;
                bL = cL; bR = cR;
            }
        }
    }

    const float bmax = block_max_256(mx);
    const int survive = (bmax >= DW_THRESH) ? 1 : 0;
    if (tid == 0) {
        g_flag[map] = survive;
        if (survive) atomicAdd(&g_surv[b], 1);
    }

    if (survive && colok) {
        float* yout = g_y + (size_t)map * HWOUT + col;
        #pragma unroll
        for (int r = 0; r < 7; r++)
            if (r < nrows)
                *(float2*)(yout + (row0 + r) * WOUT) = make_float2(vL[r], vR[r]);
    }
}

// ---------------------------------------------------------------------------
// Kernel B: pointwise GEMM + bias + BN + ReLU + cut.
// One 256-thread block per (b,o) map. cnt==0 fast path: uniform float4 fill.
// ---------------------------------------------------------------------------
__global__ __launch_bounds__(256, 8)
void pw_kernel(const float* __restrict__ pw_w,
               const float* __restrict__ pw_b,
               const float* __restrict__ pw_gamma,
               const float* __restrict__ pw_beta,
               const float* __restrict__ pw_mean,
               const float* __restrict__ pw_var,
               float* __restrict__ out)
{
    const int bo  = blockIdx.x;            // b * COUT + o
    const int o   = bo & (COUT - 1);
    const int bi  = bo >> 9;               // COUT = 512
    const int tid = threadIdx.x;

    const int cnt = g_surv[bi];

    const float scale = pw_gamma[o] * rsqrtf(pw_var[o] + EPS);
    const float shift = pw_beta[o] - pw_mean[o] * scale;
    const float bias  = pw_b[o];

    float4* op4 = (float4*)(out + (size_t)bo * HWOUT);

    if (cnt == 0) {
        // All input maps zero: z is uniform relu(bias*scale+shift); cut if < thresh.
        float v = fmaxf(fmaf(bias, scale, shift), 0.0f);
        if (v < PW_THRESH) v = 0.0f;
        const float4 val = make_float4(v, v, v, v);
        #pragma unroll
        for (int r = 0; r < 3; r++) {
            const int idx = tid + r * 256;
            if (idx < HWOUT / 4) op4[idx] = val;     // 729 float4
        }
        return;
    }

    // ---- survivor path (rare): channel GEMM over flagged channels ----
    __shared__ float wrow[CIN];
    __shared__ char  fl[CIN];
    wrow[tid] = pw_w[(size_t)o * CIN + tid];
    fl[tid]   = (char)(g_flag[bi * CIN + tid] != 0);
    __syncthreads();

    float4 acc[3];
    #pragma unroll
    for (int r = 0; r < 3; r++) acc[r] = make_float4(0.f, 0.f, 0.f, 0.f);

    for (int k = 0; k < CIN; k++) {
        if (!fl[k]) continue;
        const float wv = wrow[k];
        const float4* yr4 = (const float4*)(g_y + ((size_t)bi * CIN + k) * HWOUT);
        #pragma unroll
        for (int r = 0; r < 3; r++) {
            const int idx = tid + r * 256;
            if (idx < HWOUT / 4) {
                const float4 yv = yr4[idx];
                acc[r].x = fmaf(yv.x, wv, acc[r].x);
                acc[r].y = fmaf(yv.y, wv, acc[r].y);
                acc[r].z = fmaf(yv.z, wv, acc[r].z);
                acc[r].w = fmaf(yv.w, wv, acc[r].w);
            }
        }
    }

    float4 z[3];
    float mx = 0.0f;
    #pragma unroll
    for (int r = 0; r < 3; r++) {
        z[r].x = fmaxf(fmaf(acc[r].x + bias, scale, shift), 0.0f);
        z[r].y = fmaxf(fmaf(acc[r].y + bias, scale, shift), 0.0f);
        z[r].z = fmaxf(fmaf(acc[r].z + bias, scale, shift), 0.0f);
        z[r].w = fmaxf(fmaf(acc[r].w + bias, scale, shift), 0.0f);
        mx = fmaxf(mx, fmaxf(fmaxf(z[r].x, z[r].y), fmaxf(z[r].z, z[r].w)));
    }

    const float bmax = block_max_256(mx);
    const bool cut = (bmax < PW_THRESH);

    #pragma unroll
    for (int r = 0; r < 3; r++) {
        const int idx = tid + r * 256;
        if (idx < HWOUT / 4)
            op4[idx] = cut ? make_float4(0.f, 0.f, 0.f, 0.f) : z[r];
    }
}

// ---------------------------------------------------------------------------
extern "C" void kernel_launch(void* const* d_in, const int* in_sizes, int n_in,
                              void* d_out, int out_size)
{
    const float* x        = (const float*)d_in[0];
    const float* dw_w     = (const float*)d_in[1];
    const float* dw_b     = (const float*)d_in[2];
    const float* dw_gamma = (const float*)d_in[3];
    const float* dw_beta  = (const float*)d_in[4];
    const float* dw_mean  = (const float*)d_in[5];
    const float* dw_var   = (const float*)d_in[6];
    const float* pw_w     = (const float*)d_in[7];
    const float* pw_b     = (const float*)d_in[8];
    const float* pw_gamma = (const float*)d_in[9];
    const float* pw_beta  = (const float*)d_in[10];
    const float* pw_mean  = (const float*)d_in[11];
    const float* pw_var   = (const float*)d_in[12];
    float* out = (float*)d_out;

    init_kernel<<<1, 32>>>();
    dw_kernel<<<B_ * CIN, 256>>>(x, dw_w, dw_b, dw_gamma, dw_beta, dw_mean, dw_var);
    pw_kernel<<<B_ * COUT, 256>>>(pw_w, pw_b, pw_gamma, pw_beta, pw_mean, pw_var, out);
}